// round 17
// baseline (speedup 1.0000x reference)
#include <cuda_runtime.h>
#include <math.h>

// ---------------- problem constants ----------------
#define BB   2048          // graphs
#define NP   68            // nodes per graph
#define NC   8             // clusters
#define FH   128           // hidden
#define NN   (BB*NP)       // 139264 nodes
#define EE   (BB*NP*8)     // 1114112 edges
#define EPG  (NP*8)        // 544 edges per graph
#define GT64 (NN/64)       // 2176 M-tiles of 64 rows

typedef unsigned long long ull;
typedef unsigned int uint32;

// ---------------- scratch (device globals: no allocation allowed) ----------------
__device__ float g_P [(size_t)NN*FH];   // H @ W_rel
__device__ float g_Rb[(size_t)NN*FH];   // H @ W_root + b
__device__ float g_HA[(size_t)NN*FH];
__device__ float g_HB[(size_t)NN*FH];
// CSR: per-node in-edge lists (local src ids)
__device__ int           g_cnt[NN];
__device__ int           g_off[NN];
__device__ unsigned char g_srcs[EE];
// k-quad-major packed weights: [layer][kq*256 + f] = (W[4kq..4kq+3][f]),
// f<128 -> Wrel, f>=128 -> Wroot
__device__ float4 g_WQ[2][32*256];

// ---------------- f32x2 packed helpers ----------------
__device__ __forceinline__ void fma2(ull& d, ull a, ull b){
    asm("fma.rn.f32x2 %0, %1, %2, %0;" : "+l"(d) : "l"(a), "l"(b));
}
__device__ __forceinline__ ull pack2(uint32 lo, uint32 hi){
    ull r; asm("mov.b64 %0, {%1, %2};" : "=l"(r) : "r"(lo), "r"(hi)); return r;
}
__device__ __forceinline__ ull dup2(float x){
    ull r; asm("mov.b64 %0, {%1, %1};" : "=l"(r) : "f"(x)); return r;
}
__device__ __forceinline__ float2 unpack2(ull v){
    float2 f; asm("mov.b64 {%0, %1}, %2;" : "=f"(f.x), "=f"(f.y) : "l"(v)); return f;
}

// ---------------- single-kernel CSR build: one block per graph ----------------
__global__ void __launch_bounds__(EPG) k_csr(const int* __restrict__ ei){
    __shared__ int cnt[NP], off[NP], cur[NP];
    __shared__ unsigned char srcs[EPG];
    __shared__ int anynz;
    const int g = blockIdx.x, t = threadIdx.x;
    if (t == 0) anynz = 0;
    if (t < NP) cnt[t] = 0;
    __syncthreads();

    const size_t e = (size_t)g*EPG + t;
    if (ei[2*e + 1] != 0) atomicOr(&anynz, 1);
    __syncthreads();
    const int is64 = (anynz == 0);

    int s, d;
    if (is64){ s = ei[2*e]; d = ei[2*(EE + e)]; }
    else     { s = ei[e];   d = ei[EE + e];    }
    const int ls = s % NP;
    const int ld = d % NP;
    atomicAdd(&cnt[ld], 1);
    __syncthreads();

    if (t < 32){
        int carry = 0;
        #pragma unroll
        for (int ch = 0; ch < 3; ch++){
            int n = ch*32 + t;
            int valid = (n < NP);
            int v0 = valid ? cnt[n] : 0;
            int v = v0;
            #pragma unroll
            for (int o = 1; o < 32; o <<= 1){
                int x = __shfl_up_sync(0xffffffffu, v, o);
                if (t >= o) v += x;
            }
            if (valid){ off[n] = carry + v - v0; cur[n] = off[n]; }
            carry += __shfl_sync(0xffffffffu, v, 31);
        }
    }
    __syncthreads();

    int pos = atomicAdd(&cur[ld], 1);
    srcs[pos] = (unsigned char)ls;
    __syncthreads();

    // deterministic order: insertion-sort each node's src list
    if (t < NP){
        int o = off[t], c = cnt[t];
        for (int i = 1; i < c; i++){
            unsigned char key = srcs[o+i];
            int j = i - 1;
            while (j >= 0 && srcs[o+j] > key){ srcs[o+j+1] = srcs[o+j]; j--; }
            srcs[o+j+1] = key;
        }
    }
    __syncthreads();

    g_srcs[(size_t)g*EPG + t] = srcs[t];
    if (t < NP){
        g_off[g*NP + t] = g*EPG + off[t];
        g_cnt[g*NP + t] = cnt[t];
    }
}

// ---------------- W prep: k-quad-major packing ----------------
__global__ void k_prepW(const float* __restrict__ Wre2, const float* __restrict__ Wro2,
                        const float* __restrict__ Wre3, const float* __restrict__ Wro3){
    int idx = blockIdx.x*blockDim.x + threadIdx.x;   // 0 .. 16383
    int layer = idx >> 13;
    int r = idx & 8191;
    int kq = r >> 8, f = r & 255;
    const float* Wrel  = layer ? Wre3 : Wre2;
    const float* Wroot = layer ? Wro3 : Wro2;
    const float* W = (f < 128) ? Wrel : Wroot;
    int ff = f & 127;
    int k = kq*4;
    float4 v;
    v.x = W[(k+0)*128 + ff];
    v.y = W[(k+1)*128 + ff];
    v.z = W[(k+2)*128 + ff];
    v.w = W[(k+3)*128 + ff];
    g_WQ[layer][r] = v;
}

// ---------------- layer 1 (F_IN = 2): HA = relu(agg@Wrel + x@Wroot + b) ----------------
__global__ void k_layer1(const float* __restrict__ x,
                         const float* __restrict__ Wrel, const float* __restrict__ Wroot,
                         const float* __restrict__ b){
    __shared__ float xs[NP*2], ax[NP*2], wr[2*FH], wo[2*FH], bs[FH];
    const int g = blockIdx.x, t = threadIdx.x;
    if (t < NP*2) xs[t] = x[(size_t)g*NP*2 + t];
    if (t < FH){
        wr[t] = Wrel[t];  wr[FH+t] = Wrel[FH+t];
        wo[t] = Wroot[t]; wo[FH+t] = Wroot[FH+t];
        bs[t] = b[t];
    }
    __syncthreads();
    if (t < NP*2){
        int n = t >> 1, d = t & 1;
        int off = g_off[g*NP + n], cnt = g_cnt[g*NP + n];
        float sv = 0.0f;
        for (int i = 0; i < cnt; i++) sv += xs[((int)g_srcs[off+i])*2 + d];
        ax[t] = sv;
    }
    __syncthreads();
    for (int idx = t; idx < NP*FH; idx += blockDim.x){
        int n = idx >> 7, f = idx & 127;
        float v = ax[n*2]*wr[f] + ax[n*2+1]*wr[FH+f]
                + xs[n*2]*wo[f] + xs[n*2+1]*wo[FH+f] + bs[f];
        g_HA[(size_t)g*NP*FH + idx] = fmaxf(v, 0.0f);
    }
}

// ---------------- register-tiled half-split dual GEMM (2 CTAs/SM) ----------------
// CTA = 64 rows x 128 cols (one output half: 0 -> g_P, 1 -> g_Rb + bias).
// 8 warps in 2x4 grid, warp tile 32x32, thread tile 4 rows (rg+8i) x 8 cols (cl+4j).
// A stored TRANSPOSED k-pair-major in smem: As2[kp][row] (stride 130 floats) so A
// fragment loads are LDS.64 over 8 distinct rows (dense, conflict-free wavefronts)
// instead of 16B broadcast LDS.128. B fragments: LDS.128 over 4 distinct cols.
// Per warp per kq: 16 LDS + 64 fma2 -> fma-pipe-bound with ~2x L1 slack.
#define TST2 130
#define GEMM_SMEM ((16384 + 64*TST2 + 128)*4)

__global__ void __launch_bounds__(256, 2) k_gemm(int layer, const float* __restrict__ bias){
    extern __shared__ float sm[];
    float4* WQs = (float4*)sm;              // 4096 float4 = 64KB (this half's W, k-quad)
    float*  As2 = sm + 16384;               // 64 kp-rows x TST2 (transposed A)
    float*  bs  = As2 + 64*TST2;            // 128
    const float* __restrict__ Hin = (layer == 2) ? g_HA : g_HB;
    const int t = threadIdx.x;
    const int half = blockIdx.x & 1;
    const int nstr = gridDim.x >> 1;
    const float4* __restrict__ WQg = g_WQ[layer-2];

    // stage W half: WQs[kq*128 + f] = g_WQ[kq*256 + half*128 + f]
    for (int i = t; i < 4096; i += 256){
        int kq = i >> 7, f = i & 127;
        WQs[i] = WQg[kq*256 + half*128 + f];
    }
    if (t < 128) bs[t] = bias[t];

    const int w = t >> 5, lane = t & 31;
    const int rg = lane >> 2, cl = lane & 3;
    const int wrow = (w & 1)*32, wcol = (w >> 1)*32;
    const int frow = t >> 2, fc4 = t & 3;       // A-fill mapping
    float* __restrict__ Out = half ? g_Rb : g_P;

    for (int tile = blockIdx.x >> 1; tile < GT64; tile += nstr){
        __syncthreads();    // previous compute done (and W/bias staged on 1st iter)

        // ---- fill A transposed: As2[kp][row] = (H[row][2kp], H[row][2kp+1]) ----
        const float* Ht = Hin + (size_t)tile*64*128;
        #pragma unroll
        for (int i2 = 0; i2 < 8; i2++){
            int f4 = fc4 + 4*i2;                         // float4 index within row
            float4 v = *(const float4*)(Ht + frow*128 + f4*4);
            int kp0 = f4*2;
            *(float2*)(As2 + kp0*TST2     + frow*2) = make_float2(v.x, v.y);
            *(float2*)(As2 + (kp0+1)*TST2 + frow*2) = make_float2(v.z, v.w);
        }
        __syncthreads();

        ull acc[4][8];
        #pragma unroll
        for (int i = 0; i < 4; i++)
            #pragma unroll
            for (int j = 0; j < 8; j++) acc[i][j] = 0ULL;

        #pragma unroll 4
        for (int kq = 0; kq < 32; kq++){
            // A fragments: LDS.64, 8 distinct rows per instr (conflict-free)
            ull a01[4], a23[4];
            #pragma unroll
            for (int i = 0; i < 4; i++){
                int r = wrow + rg + 8*i;
                a01[i] = *(const ull*)(As2 + (2*kq  )*TST2 + r*2);
                a23[i] = *(const ull*)(As2 + (2*kq+1)*TST2 + r*2);
            }
            #pragma unroll
            for (int jc = 0; jc < 2; jc++){
                uint4 bq[4];
                #pragma unroll
                for (int j = 0; j < 4; j++)
                    bq[j] = *(const uint4*)(WQs + kq*128 + wcol + cl + 4*(jc*4 + j));
                #pragma unroll
                for (int i = 0; i < 4; i++)
                    #pragma unroll
                    for (int j = 0; j < 4; j++){
                        fma2(acc[i][jc*4+j], a01[i], pack2(bq[j].x, bq[j].y));
                        fma2(acc[i][jc*4+j], a23[i], pack2(bq[j].z, bq[j].w));
                    }
            }
        }

        // ---- epilogue ----
        #pragma unroll
        for (int i = 0; i < 4; i++){
            size_t row = (size_t)tile*64 + wrow + rg + 8*i;
            #pragma unroll
            for (int j = 0; j < 8; j++){
                int col = wcol + cl + 4*j;
                float2 p = unpack2(acc[i][j]);
                Out[row*128 + col] = p.x + p.y + (half ? bs[col] : 0.0f);
            }
        }
    }
}

// ---------------- conv-apply (sparse): H_out = relu(sum_{j->n} P_j + Rb_n) ----------------
#define PST 130
__global__ void __launch_bounds__(544) k_conv(int layer){
    __shared__ float Ps[NP*PST];
    const int g = blockIdx.x, t = threadIdx.x;
    float* __restrict__ Hout = (layer == 2) ? g_HB : g_HA;

    const float* Pg = g_P + (size_t)g*NP*FH;
    for (int i = t; i < NP*FH; i += 544){
        int row = i >> 7, col = i & 127;
        Ps[row*PST + col] = Pg[i];
    }
    __syncthreads();

    const int n  = t >> 3;     // 0..67
    const int cg = t & 7;      // 0..7 -> pair cols cg + 8u
    const int off = g_off[g*NP + n];
    const int cnt = g_cnt[g*NP + n];

    const float* rb = g_Rb + ((size_t)g*NP + n)*FH;
    ull acc[8];
    #pragma unroll
    for (int u = 0; u < 8; u++) acc[u] = *(const ull*)(rb + 2*(cg + 8*u));

    const ull one = dup2(1.0f);
    for (int e = 0; e < cnt; e++){
        const float* pr = Ps + ((int)g_srcs[off+e])*PST;
        #pragma unroll
        for (int u = 0; u < 8; u++){
            ull pv = *(const ull*)(pr + 2*(cg + 8*u));
            fma2(acc[u], one, pv);
        }
    }
    float* ho = Hout + ((size_t)g*NP + n)*FH;
    #pragma unroll
    for (int u = 0; u < 8; u++){
        float2 v = unpack2(acc[u]);
        v.x = fmaxf(v.x, 0.0f); v.y = fmaxf(v.y, 0.0f);
        *(float2*)(ho + 2*(cg + 8*u)) = v;
    }
}

// ---------------- pool: softmax(s) einsum, maxpool(1,8), fc ----------------
__global__ void __launch_bounds__(512) k_pool(const float* __restrict__ s_in,
                       const float* __restrict__ fcw, const float* __restrict__ fcb,
                       float* __restrict__ out){
    __shared__ float Hs[NP*FH];
    __shared__ float ssm[NP*NC];
    __shared__ float xp[NC*FH];
    __shared__ float red[128];
    const int g = blockIdx.x, t = threadIdx.x;

    const float* Hg = g_HA + (size_t)g*NP*FH;
    for (int i = t; i < NP*FH; i += 512) Hs[i] = Hg[i];

    if (t < NP){
        float v[NC]; float m = -1e30f;
        #pragma unroll
        for (int k = 0; k < NC; k++){ v[k] = s_in[((size_t)g*NP + t)*NC + k]; m = fmaxf(m, v[k]); }
        float sum = 0.0f;
        #pragma unroll
        for (int k = 0; k < NC; k++){ v[k] = expf(v[k]-m); sum += v[k]; }
        float inv = 1.0f/sum;
        #pragma unroll
        for (int k = 0; k < NC; k++) ssm[t*NC+k] = v[k]*inv;
    }
    __syncthreads();

    for (int idx = t; idx < NC*FH; idx += 512){
        int c = idx >> 7, f = idx & 127;
        float acc = 0.0f;
        #pragma unroll 4
        for (int n = 0; n < NP; n++) acc += ssm[n*NC+c] * Hs[n*FH + f];
        xp[c*FH + f] = acc;
    }
    __syncthreads();

    if (t < 128){
        int c = t >> 4, j = t & 15;
        float m = xp[c*FH + j*8];
        #pragma unroll
        for (int u = 1; u < 8; u++) m = fmaxf(m, xp[c*FH + j*8 + u]);
        red[t] = m * fcw[t];
    }
    __syncthreads();
    if (t < 64) red[t] += red[t+64];
    __syncthreads();
    if (t < 32){
        float v = red[t] + red[t+32];
        #pragma unroll
        for (int o = 16; o; o >>= 1) v += __shfl_down_sync(0xffffffffu, v, o);
        if (t == 0) out[g] = v + fcb[0];
    }
}

// ---------------- launch ----------------
extern "C" void kernel_launch(void* const* d_in, const int* in_sizes, int n_in,
                              void* d_out, int out_size){
    const float* x    = (const float*)d_in[0];
    const int*   ei   = (const int*)  d_in[1];
    // d_in[2] = adj : unused (pool losses are discarded in reference)
    const float* s_in = (const float*)d_in[3];
    const float* Wro1 = (const float*)d_in[4];
    const float* Wre1 = (const float*)d_in[5];
    const float* b1   = (const float*)d_in[6];
    const float* Wro2 = (const float*)d_in[7];
    const float* Wre2 = (const float*)d_in[8];
    const float* b2   = (const float*)d_in[9];
    const float* Wro3 = (const float*)d_in[10];
    const float* Wre3 = (const float*)d_in[11];
    const float* b3   = (const float*)d_in[12];
    const float* fcw  = (const float*)d_in[13];
    const float* fcb  = (const float*)d_in[14];
    float* out = (float*)d_out;
    (void)in_sizes; (void)n_in; (void)out_size;

    cudaFuncSetAttribute(k_gemm, cudaFuncAttributeMaxDynamicSharedMemorySize, GEMM_SMEM);

    k_csr<<<BB, EPG>>>(ei);
    k_prepW<<<64, 256>>>(Wre2, Wro2, Wre3, Wro3);

    k_layer1<<<BB, 256>>>(x, Wre1, Wro1, b1);                 // -> g_HA

    k_gemm<<<592, 256, GEMM_SMEM>>>(2, b2);                   // g_HA -> g_P, g_Rb
    k_conv<<<BB, 544>>>(2);                                   // -> g_HB

    k_gemm<<<592, 256, GEMM_SMEM>>>(3, b3);                   // g_HB -> g_P, g_Rb
    k_conv<<<BB, 544>>>(3);                                   // -> g_HA

    k_pool<<<BB, 512>>>(s_in, fcw, fcb, out);
}